// round 6
// baseline (speedup 1.0000x reference)
#include <cuda_runtime.h>
#include <cstdint>

// ---------------------------------------------------------------------------
// CIF (continuous integrate-and-fire) — minimal-work exact replay.
//
// Outputs (concatenated fp32, reference return order):
//   frame_sel [T,H]  : frames of batch 0 gathered at fire indices, padded
//                      with frames[0][0]
//   integ_new [B]
//   frame_new [B,H]
//
// Key facts exploited:
//  * integ/fire recurrence depends only on alphas  -> scalar scan, 1 warp,
//    lane = batch
//  * frames[0][t] needed only at fire indices (+ t=0) -> short segment sums
//  * frame_new[b] needs only the post-last-fire tail
//  * fire decisions MUST be bit-exact fp32 replays of the reference:
//      s = integ + a ; fire = (s >= 1) ; integ' = fire ? s-1 : s
//    (s-1 is Sterbenz-exact for s in [1,2), so recomputing integ' from a
//     recorded s is bit-identical)
// ---------------------------------------------------------------------------

#define CIF_MAX_T 2048
#define CIF_MAX_B 64

__device__ __align__(16) float d_cur0[CIF_MAX_T];     // cur weights, batch 0
__device__ int   d_fireIdx[CIF_MAX_T];                // ascending fire indices, batch 0
__device__ float d_remList[CIF_MAX_T];                // rem at each fire, batch 0
__device__ int   d_F;                                 // number of fires, batch 0
__device__ int   d_lastFire[CIF_MAX_B];               // last fire index per batch (-1 none)
__device__ float d_lastPrev[CIF_MAX_B];               // integ before the last fire step
__device__ float d_lastA[CIF_MAX_B];                  // alpha at the last fire step

// One recurrence step, bit-exact vs reference.
__device__ __forceinline__ float cif_step(float a, int tt, float& integ,
                                          float& lastPrev, float& lastAv, int& lastF)
{
    float s = integ + a;
    bool  f = (s >= 1.0f);
    float c = s - 1.0f;          // exact when f (Sterbenz)
    lastPrev = f ? integ : lastPrev;
    lastAv   = f ? a     : lastAv;
    lastF    = f ? tt    : lastF;
    integ    = f ? c     : s;
    return s;
}

// ---------------------------------------------------------------------------
// Kernel 1: one block.
//   Phase A (warp 0, lane b = batch b): sequential scan over T steps.
//            Lane 0 records s_t (batch 0) into shared memory (STS.128 / 4 steps).
//   Phase B (all 256 threads): derive fire/cur/rem for batch 0 from the s
//            sequence (exact), compact the fire list via a block scan.
// ---------------------------------------------------------------------------
__global__ __launch_bounds__(256, 1)
void cif_scan_kernel(const float* __restrict__ alphas,
                     const float* __restrict__ integrate,
                     float* __restrict__ out_integ,   // = out + T*H
                     int B, int T)
{
    __shared__ float smem_s[CIF_MAX_T];
    __shared__ int   smem_scan[256];

    const int tid = threadIdx.x;

    // ---------------- Phase A: sequential scan (warp 0) ----------------
    if (tid < B) {
        const int b = tid;
        const int q4 = T >> 2;  // float4 per row
        const float4* __restrict__ arow =
            reinterpret_cast<const float4*>(alphas) + (size_t)b * q4;

        float integ    = integrate[b];
        float lastPrev = 0.0f, lastAv = 0.0f;
        int   lastF    = -1;

        // 64-step chunks, double-buffered in registers: prefetch distance
        // = 64 steps * ~12 cyc = 768 cycles > 577-cycle DRAM latency.
        float4 bufA[16], bufB[16];
        #pragma unroll
        for (int i = 0; i < 16; ++i) { int idx = i; bufA[i] = arow[idx < q4 ? idx : q4 - 1]; }

        int t = 0;
        const int npairs = T >> 7;   // T / 128

#define CIF_PROCESS16(BUF)                                                          \
        do {                                                                        \
            _Pragma("unroll")                                                       \
            for (int i = 0; i < 16; ++i) {                                          \
                float4 a4 = (BUF)[i];                                               \
                float s0 = cif_step(a4.x, t + 0, integ, lastPrev, lastAv, lastF);   \
                float s1 = cif_step(a4.y, t + 1, integ, lastPrev, lastAv, lastF);   \
                float s2 = cif_step(a4.z, t + 2, integ, lastPrev, lastAv, lastF);   \
                float s3 = cif_step(a4.w, t + 3, integ, lastPrev, lastAv, lastF);   \
                if (b == 0)                                                         \
                    *reinterpret_cast<float4*>(&smem_s[t]) =                        \
                        make_float4(s0, s1, s2, s3);                                \
                t += 4;                                                             \
            }                                                                       \
        } while (0)

        for (int cp = 0; cp < npairs; ++cp) {
            int nb = (cp * 2 + 1) * 16;
            #pragma unroll
            for (int i = 0; i < 16; ++i) { int idx = nb + i; bufB[i] = arow[idx < q4 ? idx : q4 - 1]; }
            CIF_PROCESS16(bufA);
            int na = (cp * 2 + 2) * 16;
            #pragma unroll
            for (int i = 0; i < 16; ++i) { int idx = na + i; bufA[i] = arow[idx < q4 ? idx : q4 - 1]; }
            CIF_PROCESS16(bufB);
        }
#undef CIF_PROCESS16

        d_lastFire[b] = lastF;
        d_lastPrev[b] = lastPrev;
        d_lastA[b]    = lastAv;
        out_integ[b]  = integ;          // integ_new output
    }
    __syncthreads();

    // ---------------- Phase B: derive + compact (all 256 threads) ----------------
    // Each thread covers 8 consecutive t (T = 2048).
    const int t0 = tid * 8;
    const float integ0 = integrate[0];

    float rems[8];
    int   flgmask = 0;
    int   cnt = 0;

    if (t0 < T) {
        #pragma unroll
        for (int k = 0; k < 8; ++k) {
            int t = t0 + k;
            float s = smem_s[t];
            float integPrev;
            if (t == 0) {
                integPrev = integ0;
            } else {
                float sp = smem_s[t - 1];
                integPrev = (sp >= 1.0f) ? (sp - 1.0f) : sp;   // exact replay
            }
            bool  f    = (s >= 1.0f);
            float a    = alphas[t];                 // batch 0 row
            float dist = 1.0f - integPrev;          // reference op order
            float cur  = f ? dist : a;
            float rem  = a - cur;                   // reference op order
            d_cur0[t]  = cur;
            rems[k]    = rem;
            if (f) { flgmask |= (1 << k); cnt++; }
        }
    }

    // Inclusive Hillis–Steele scan over per-thread fire counts.
    smem_scan[tid] = cnt;
    __syncthreads();
    #pragma unroll
    for (int off = 1; off < 256; off <<= 1) {
        int v = 0;
        if (tid >= off) v = smem_scan[tid - off];
        __syncthreads();
        smem_scan[tid] += v;
        __syncthreads();
    }
    int offset = smem_scan[tid] - cnt;   // exclusive prefix
    int total  = smem_scan[255];

    if (t0 < T) {
        #pragma unroll
        for (int k = 0; k < 8; ++k) {
            if (flgmask & (1 << k)) {
                d_fireIdx[offset] = t0 + k;
                d_remList[offset] = rems[k];
                offset++;
            }
        }
    }
    if (tid == 0) d_F = total;
}

// ---------------------------------------------------------------------------
// Kernel 2: grid = T + B blocks, H threads.
//   blocks [0, T)   : frame_sel rows (segment-weighted sums of hidden[0])
//   blocks [T, T+B) : frame_new per batch (tail after last fire)
// ---------------------------------------------------------------------------
__global__ __launch_bounds__(512, 4)
void cif_frames_kernel(const float* __restrict__ hidden,
                       const float* __restrict__ alphas,
                       const float* __restrict__ frame_init,
                       float* __restrict__ out,
                       int B, int T, int H)
{
    const int h = threadIdx.x;
    const int j = blockIdx.x;

    if (j < T) {
        const int F = d_F;
        if (j < F) {
            int   tj = d_fireIdx[j];
            int   start;
            float acc;
            if (j == 0) {
                acc   = frame_init[h];                 // batch 0 initial frame
                start = 0;
            } else {
                int tp = d_fireIdx[j - 1];
                acc   = d_remList[j - 1] * hidden[(size_t)tp * H + h];
                start = tp + 1;
            }
            for (int t = start; t <= tj; ++t)
                acc += d_cur0[t] * hidden[(size_t)t * H + h];
            out[(size_t)j * H + h] = acc;
        } else {
            // padded rows replicate frames[0][0] = frame_init + cur0[0]*h[0,0]
            out[(size_t)j * H + h] = frame_init[h] + d_cur0[0] * hidden[h];
        }
    } else {
        const int b = j - T;
        const int L = d_lastFire[b];
        const float* __restrict__ hb = hidden + (size_t)b * T * H;
        const float* __restrict__ ab = alphas + (size_t)b * T;
        float acc;
        int   start;
        if (L < 0) {
            acc   = frame_init[(size_t)b * H + h];
            start = 0;
        } else {
            float dist = 1.0f - d_lastPrev[b];     // replicate reference fp32 ops
            float rem  = d_lastA[b] - dist;
            acc   = rem * hb[(size_t)L * H + h];
            start = L + 1;
        }
        for (int t = start; t < T; ++t)
            acc += ab[t] * hb[(size_t)t * H + h];
        out[(size_t)T * H + B + (size_t)b * H + h] = acc;
    }
}

// ---------------------------------------------------------------------------
// kernel_launch
// ---------------------------------------------------------------------------
extern "C" void kernel_launch(void* const* d_in, const int* in_sizes, int n_in,
                              void* d_out, int out_size)
{
    const float* hidden    = (const float*)d_in[0];   // [B,T,H]
    const float* alphas    = (const float*)d_in[1];   // [B,T]
    const float* integrate = (const float*)d_in[2];   // [B]
    const float* frame     = (const float*)d_in[3];   // [B,H]
    float* out = (float*)d_out;

    const int B = in_sizes[2];
    const int T = in_sizes[1] / B;
    const int H = in_sizes[3] / B;

    // Kernel 1: scalar scan + derive/compact (single block).
    cif_scan_kernel<<<1, 256>>>(alphas, integrate, out + (size_t)T * H, B, T);

    // Kernel 2: frame_sel rows + frame_new tails.
    cif_frames_kernel<<<T + B, H>>>(hidden, alphas, frame, out, B, T, H);
}

// round 14
// speedup vs baseline: 1.0426x; 1.0426x over previous
#include <cuda_runtime.h>
#include <cstdint>

// ---------------------------------------------------------------------------
// CIF (continuous integrate-and-fire) — minimal-work exact replay.
//
// Outputs (concatenated fp32): frame_sel [T,H] | integ_new [B] | frame_new [B,H]
//
// R6 changes (from first profile, 36.8us total):
//  * scan: force pred-as-DATA selects (selp) — ptxas's @P-predicated moves put
//    the 13-cyc pred-as-guard latency on the chain (measured ~21 cyc/step);
//    FSEL data path restores the 12-cyc FADD->FSETP->FSEL floor.
//  * frames: 512-thr blocks gave only ~4 CTA/SM -> 3.5 waves of ~1us dependent
//    LDG chains (10.2us). Switch to 128 threads x float4 -> 16 CTA/SM ->
//    single wave; all chains overlap.
// ---------------------------------------------------------------------------

#define CIF_MAX_T 2048
#define CIF_MAX_B 64

__device__ __align__(16) float d_cur0[CIF_MAX_T];     // cur weights, batch 0
__device__ int   d_fireIdx[CIF_MAX_T];                // ascending fire indices, batch 0
__device__ float d_remList[CIF_MAX_T];                // rem at each fire, batch 0
__device__ int   d_F;                                 // number of fires, batch 0
__device__ int   d_lastFire[CIF_MAX_B];               // last fire index per batch (-1 none)
__device__ float d_lastPrev[CIF_MAX_B];               // integ before the last fire step
__device__ float d_lastA[CIF_MAX_B];                  // alpha at the last fire step

// One recurrence step, bit-exact vs reference:
//   s = integ + a ; fire = (s >= 1) ; integ' = fire ? s-1 : s  (Sterbenz-exact)
// selp forces SEL/FSEL (pred-as-data, 4 cyc) instead of @P moves (13 cyc guard).
__device__ __forceinline__ float cif_step(float a, int tt, float& integ,
                                          float& lastPrev, float& lastAv, int& lastF)
{
    float s = integ + a;
    float c = s - 1.0f;          // exact when fire (Sterbenz)
    float ni, nlp, nla; int nlf;
    asm("{\n\t"
        ".reg .pred p;\n\t"
        "setp.ge.f32 p, %4, 0f3F800000;\n\t"
        "selp.f32 %0, %5, %4, p;\n\t"      // integ' = p ? c : s   (critical path)
        "selp.f32 %1, %6, %7, p;\n\t"      // lastPrev
        "selp.f32 %2, %8, %9, p;\n\t"      // lastA
        "selp.b32 %3, %10, %11, p;\n\t"    // lastF
        "}"
        : "=f"(ni), "=f"(nlp), "=f"(nla), "=r"(nlf)
        : "f"(s), "f"(c), "f"(integ), "f"(lastPrev), "f"(a), "f"(lastAv),
          "r"(tt), "r"(lastF));
    integ = ni; lastPrev = nlp; lastAv = nla; lastF = nlf;
    return s;
}

// ---------------------------------------------------------------------------
// Kernel 1: one block.
//   Phase A (warp 0, lane b = batch b): sequential scan over T steps.
//            Lane 0 records s_t (batch 0) into shared memory (STS.128 / 4 steps).
//   Phase B (all 256 threads): derive fire/cur/rem for batch 0 from the s
//            sequence (exact), compact the fire list via a block scan.
// ---------------------------------------------------------------------------
__global__ __launch_bounds__(256, 1)
void cif_scan_kernel(const float* __restrict__ alphas,
                     const float* __restrict__ integrate,
                     float* __restrict__ out_integ,   // = out + T*H
                     int B, int T)
{
    __shared__ float smem_s[CIF_MAX_T];
    __shared__ int   smem_scan[256];

    const int tid = threadIdx.x;

    // ---------------- Phase A: sequential scan (warp 0) ----------------
    if (tid < B) {
        const int b = tid;
        const int q4 = T >> 2;  // float4 per row
        const float4* __restrict__ arow =
            reinterpret_cast<const float4*>(alphas) + (size_t)b * q4;

        float integ    = integrate[b];
        float lastPrev = 0.0f, lastAv = 0.0f;
        int   lastF    = -1;

        // 64-step chunks, double-buffered in registers: prefetch distance
        // = 64 steps * ~12 cyc = 768 cycles > DRAM latency.
        float4 bufA[16], bufB[16];
        #pragma unroll
        for (int i = 0; i < 16; ++i) { int idx = i; bufA[i] = arow[idx < q4 ? idx : q4 - 1]; }

        int t = 0;
        const int npairs = T >> 7;   // T / 128

#define CIF_PROCESS16(BUF)                                                          \
        do {                                                                        \
            _Pragma("unroll")                                                       \
            for (int i = 0; i < 16; ++i) {                                          \
                float4 a4 = (BUF)[i];                                               \
                float s0 = cif_step(a4.x, t + 0, integ, lastPrev, lastAv, lastF);   \
                float s1 = cif_step(a4.y, t + 1, integ, lastPrev, lastAv, lastF);   \
                float s2 = cif_step(a4.z, t + 2, integ, lastPrev, lastAv, lastF);   \
                float s3 = cif_step(a4.w, t + 3, integ, lastPrev, lastAv, lastF);   \
                if (b == 0)                                                         \
                    *reinterpret_cast<float4*>(&smem_s[t]) =                        \
                        make_float4(s0, s1, s2, s3);                                \
                t += 4;                                                             \
            }                                                                       \
        } while (0)

        for (int cp = 0; cp < npairs; ++cp) {
            int nb = (cp * 2 + 1) * 16;
            #pragma unroll
            for (int i = 0; i < 16; ++i) { int idx = nb + i; bufB[i] = arow[idx < q4 ? idx : q4 - 1]; }
            CIF_PROCESS16(bufA);
            int na = (cp * 2 + 2) * 16;
            #pragma unroll
            for (int i = 0; i < 16; ++i) { int idx = na + i; bufA[i] = arow[idx < q4 ? idx : q4 - 1]; }
            CIF_PROCESS16(bufB);
        }
#undef CIF_PROCESS16

        d_lastFire[b] = lastF;
        d_lastPrev[b] = lastPrev;
        d_lastA[b]    = lastAv;
        out_integ[b]  = integ;          // integ_new output
    }
    __syncthreads();

    // ---------------- Phase B: derive + compact (all 256 threads) ----------------
    const int t0 = tid * 8;
    const float integ0 = integrate[0];

    float rems[8];
    int   flgmask = 0;
    int   cnt = 0;

    if (t0 < T) {
        #pragma unroll
        for (int k = 0; k < 8; ++k) {
            int t = t0 + k;
            float s = smem_s[t];
            float integPrev;
            if (t == 0) {
                integPrev = integ0;
            } else {
                float sp = smem_s[t - 1];
                integPrev = (sp >= 1.0f) ? (sp - 1.0f) : sp;   // exact replay
            }
            bool  f    = (s >= 1.0f);
            float a    = alphas[t];                 // batch 0 row
            float dist = 1.0f - integPrev;          // reference op order
            float cur  = f ? dist : a;
            float rem  = a - cur;                   // reference op order
            d_cur0[t]  = cur;
            rems[k]    = rem;
            if (f) { flgmask |= (1 << k); cnt++; }
        }
    }

    // Inclusive Hillis–Steele scan over per-thread fire counts.
    smem_scan[tid] = cnt;
    __syncthreads();
    #pragma unroll
    for (int off = 1; off < 256; off <<= 1) {
        int v = 0;
        if (tid >= off) v = smem_scan[tid - off];
        __syncthreads();
        smem_scan[tid] += v;
        __syncthreads();
    }
    int offset = smem_scan[tid] - cnt;   // exclusive prefix
    int total  = smem_scan[255];

    if (t0 < T) {
        #pragma unroll
        for (int k = 0; k < 8; ++k) {
            if (flgmask & (1 << k)) {
                d_fireIdx[offset] = t0 + k;
                d_remList[offset] = rems[k];
                offset++;
            }
        }
    }
    if (tid == 0) d_F = total;
}

// ---------------------------------------------------------------------------
// Kernel 2: grid = T + B blocks, 128 threads; each thread owns 4 h via float4.
//   blocks [0, T)   : frame_sel rows (segment-weighted sums of hidden[0])
//   blocks [T, T+B) : frame_new per batch (tail after last fire)
// 128-thr blocks -> 16 CTA/SM -> the whole grid fits ONE wave; per-block
// dependent LDG chains (metadata -> hidden) overlap across 2080 blocks.
// ---------------------------------------------------------------------------
__global__ __launch_bounds__(128, 16)
void cif_frames_kernel(const float* __restrict__ hidden,
                       const float* __restrict__ alphas,
                       const float* __restrict__ frame_init,
                       float* __restrict__ out,
                       int B, int T, int H)
{
    const int h4 = threadIdx.x;          // 0..H/4-1
    const int j  = blockIdx.x;
    const int H4 = H >> 2;

    const float4* __restrict__ hid4 = reinterpret_cast<const float4*>(hidden);
    const float4* __restrict__ fi4  = reinterpret_cast<const float4*>(frame_init);
    float4* __restrict__ out4       = reinterpret_cast<float4*>(out);

    if (j < T) {
        const int F = d_F;
        float4 acc;
        if (j < F) {
            int tj = d_fireIdx[j];
            int start;
            if (j == 0) {
                acc   = fi4[h4];                       // batch 0 initial frame
                start = 0;
            } else {
                int   tp = d_fireIdx[j - 1];
                float r  = d_remList[j - 1];
                float4 hv = hid4[(size_t)tp * H4 + h4];
                acc.x = r * hv.x; acc.y = r * hv.y; acc.z = r * hv.z; acc.w = r * hv.w;
                start = tp + 1;
            }
            for (int t = start; t <= tj; ++t) {
                float  c  = d_cur0[t];
                float4 hv = hid4[(size_t)t * H4 + h4];
                acc.x += c * hv.x; acc.y += c * hv.y;
                acc.z += c * hv.z; acc.w += c * hv.w;
            }
            out4[(size_t)j * H4 + h4] = acc;
        } else {
            // padded rows replicate frames[0][0] = frame_init + cur0[0]*h[0,0]
            float  c0 = d_cur0[0];
            float4 hv = hid4[h4];
            float4 fi = fi4[h4];
            acc.x = fi.x + c0 * hv.x; acc.y = fi.y + c0 * hv.y;
            acc.z = fi.z + c0 * hv.z; acc.w = fi.w + c0 * hv.w;
            out4[(size_t)j * H4 + h4] = acc;
        }
    } else {
        const int b = j - T;
        const int L = d_lastFire[b];
        const float4* __restrict__ hb4 = hid4 + (size_t)b * T * H4;
        const float*  __restrict__ ab  = alphas + (size_t)b * T;
        float4 acc;
        int    start;
        if (L < 0) {
            acc   = fi4[(size_t)b * H4 + h4];
            start = 0;
        } else {
            float dist = 1.0f - d_lastPrev[b];     // replicate reference fp32 ops
            float rem  = d_lastA[b] - dist;
            float4 hv  = hb4[(size_t)L * H4 + h4];
            acc.x = rem * hv.x; acc.y = rem * hv.y;
            acc.z = rem * hv.z; acc.w = rem * hv.w;
            start = L + 1;
        }
        for (int t = start; t < T; ++t) {
            float  a  = ab[t];
            float4 hv = hb4[(size_t)t * H4 + h4];
            acc.x += a * hv.x; acc.y += a * hv.y;
            acc.z += a * hv.z; acc.w += a * hv.w;
        }
        // out offset T*H + B is 16B-aligned (B=32)
        out4[((size_t)T * H + B) / 4 + (size_t)b * H4 + h4] = acc;
    }
}

// ---------------------------------------------------------------------------
// kernel_launch
// ---------------------------------------------------------------------------
extern "C" void kernel_launch(void* const* d_in, const int* in_sizes, int n_in,
                              void* d_out, int out_size)
{
    const float* hidden    = (const float*)d_in[0];   // [B,T,H]
    const float* alphas    = (const float*)d_in[1];   // [B,T]
    const float* integrate = (const float*)d_in[2];   // [B]
    const float* frame     = (const float*)d_in[3];   // [B,H]
    float* out = (float*)d_out;

    const int B = in_sizes[2];
    const int T = in_sizes[1] / B;
    const int H = in_sizes[3] / B;

    // Kernel 1: scalar scan + derive/compact (single block).
    cif_scan_kernel<<<1, 256>>>(alphas, integrate, out + (size_t)T * H, B, T);

    // Kernel 2: frame_sel rows + frame_new tails (single wave).
    cif_frames_kernel<<<T + B, 128>>>(hidden, alphas, frame, out, B, T, H);
}